// round 12
// baseline (speedup 1.0000x reference)
#include <cuda_runtime.h>
#include <cuda_fp16.h>
#include <math.h>

// ---------------- problem constants ----------------
#define TSEQ   2048
#define BATCH  2
#define EMB    1024
#define HEADS  16
#define HDIM   64
#define BHX    (BATCH*HEADS)     // 32
#define NROWS  (BATCH*TSEQ)      // 4096
#define KTOP   512               // top 50% of 1024

// ---------------- scratch (device globals, no allocation) ----------------
__device__ float g_proj[3][NROWS][EMB];                       // 48 MB  : QKV projection outputs (b,t,e)
__device__ float g_qkvh[3][BHX][TSEQ][HDIM];                  // 48 MB  : pruned+rotated, split-head layout
__device__ float g_scores[BHX][TSEQ][TSEQ];                   // 512 MB : raw attention scores
__device__ float g_attn[NROWS][EMB];                          // 16 MB  : PV output, merged heads
__device__ float g_sinq[TSEQ][32], g_cosq[TSEQ][32];          // xpos tables (q, downscale=False)
__device__ float g_sink[TSEQ][32], g_cosk[TSEQ][32];          // xpos tables (k, downscale=True)

// ---------------- xpos table build (double precision, emulating ref fp32 rounding points) ---
__global__ void xpos_table_kernel() {
    int t = blockIdx.x;          // 0..2047
    int j = threadIdx.x;         // 0..31 (pair index)
    // base_scale computed in fp32 by the reference
    float basef = (2.0f * (float)j + 0.4f * 64.0f) / (1.4f * 64.0f);
    double power = ((double)t - 1024.0) / 512.0;     // (t - T//2)/SCALE_BASE, exact
    double scale = pow((double)basef, power);
    // inv_freq: fp32 in reference; sinusoid = (fp32 t) * (fp32 inv_freq) -> fp32 product
    float invff = (float)(1.0 / pow(10000.0, (double)j / 32.0));
    float angf  = (float)t * invff;                  // fp32 rounding matches reference
    double s = sin((double)angf);
    double c = cos((double)angf);
    g_sinq[t][j] = (float)(s * scale);
    g_cosq[t][j] = (float)(c * scale);
    g_sink[t][j] = (float)(s / scale);               // downscale: scale -> 1/scale
    g_cosk[t][j] = (float)(c / scale);
}

// ---------------- generic fp32 GEMM: C[m,n] = sum_k A[m,k]*B[n,k] (+bias[n]) -------------
// A: M x K row-major, B: N x K row-major (i.e. X @ W^T shape), batched via blockIdx.z strides.
// BM=BN=128, BK=8, 256 threads, 8x8 per thread. All dims are multiples of tile sizes here.
__global__ __launch_bounds__(256)
void sgemm_nt(const float* __restrict__ A, const float* __restrict__ Bm,
              const float* __restrict__ bias, float* __restrict__ C,
              int M, int N, int K,
              long strideA, long strideB, long strideC)
{
    __shared__ float As[8][128];
    __shared__ float Bs[8][128];
    A  += (long)blockIdx.z * strideA;
    Bm += (long)blockIdx.z * strideB;
    C  += (long)blockIdx.z * strideC;

    const int tid = threadIdx.x;
    const int loadRow = tid >> 1;          // 0..127
    const int loadCol = (tid & 1) * 4;     // 0 or 4
    const float* Ap = A  + (size_t)(blockIdx.y * 128 + loadRow) * K + loadCol;
    const float* Bp = Bm + (size_t)(blockIdx.x * 128 + loadRow) * K + loadCol;

    const int tx = tid & 15;               // 0..15 -> n
    const int ty = tid >> 4;               // 0..15 -> m

    float acc[8][8];
#pragma unroll
    for (int i = 0; i < 8; i++)
#pragma unroll
        for (int j = 0; j < 8; j++) acc[i][j] = 0.0f;

    for (int k0 = 0; k0 < K; k0 += 8) {
        float4 a = *(const float4*)(Ap + k0);
        float4 b = *(const float4*)(Bp + k0);
        As[loadCol + 0][loadRow] = a.x;
        As[loadCol + 1][loadRow] = a.y;
        As[loadCol + 2][loadRow] = a.z;
        As[loadCol + 3][loadRow] = a.w;
        Bs[loadCol + 0][loadRow] = b.x;
        Bs[loadCol + 1][loadRow] = b.y;
        Bs[loadCol + 2][loadRow] = b.z;
        Bs[loadCol + 3][loadRow] = b.w;
        __syncthreads();
#pragma unroll
        for (int kk = 0; kk < 8; kk++) {
            __align__(16) float ar[8], br[8];
            *(float4*)&ar[0] = *(const float4*)&As[kk][ty * 8];
            *(float4*)&ar[4] = *(const float4*)&As[kk][ty * 8 + 4];
            *(float4*)&br[0] = *(const float4*)&Bs[kk][tx * 8];
            *(float4*)&br[4] = *(const float4*)&Bs[kk][tx * 8 + 4];
#pragma unroll
            for (int i = 0; i < 8; i++)
#pragma unroll
                for (int j = 0; j < 8; j++)
                    acc[i][j] = fmaf(ar[i], br[j], acc[i][j]);
        }
        __syncthreads();
    }

    const int cm = blockIdx.y * 128 + ty * 8;
    const int cn = blockIdx.x * 128 + tx * 8;
    float bv[8];
#pragma unroll
    for (int j = 0; j < 8; j++) bv[j] = bias ? bias[cn + j] : 0.0f;
#pragma unroll
    for (int i = 0; i < 8; i++) {
        float* cp = C + (size_t)(cm + i) * N + cn;
#pragma unroll
        for (int j = 0; j < 8; j++) cp[j] = acc[i][j] + bv[j];
    }
}

// ---------------- pruning (exact k-th largest) + xpos + split-heads ----------------------
// One block per (row n, tensor sel). top_k keeps the 512 largest VALUES; with continuous
// random data ties have measure zero, so mask == (x >= 512th-largest). Binary search in
// monotone float->uint key space gives the exact threshold in <=32 count passes over smem.
__global__ __launch_bounds__(256)
void prune_xpos_kernel() {
    const int n   = blockIdx.x;        // 0..4095
    const int sel = blockIdx.y;        // 0=q, 1=k, 2=v
    const int b   = n >> 11;
    const int t   = n & (TSEQ - 1);
    const int tid = threadIdx.x;

    __shared__ float    row[EMB];
    __shared__ unsigned key[EMB];
    __shared__ int      cnt;

    const float scl = (sel == 0) ? 0.125f : 1.0f;   // q * D^-0.5 before pruning
#pragma unroll
    for (int i = tid; i < EMB; i += 256) {
        float x = g_proj[sel][n][i] * scl;
        row[i] = x;
        unsigned u = __float_as_uint(x);
        key[i] = (u & 0x80000000u) ? ~u : (u | 0x80000000u);
    }
    __syncthreads();

    unsigned lo = 0u, hi = 0xFFFFFFFFu;
    while (lo < hi) {                       // uniform across block (shared cnt)
        unsigned mid = lo + ((hi - lo) >> 1) + 1u;
        if (tid == 0) cnt = 0;
        __syncthreads();
        int c = 0;
        for (int i = tid; i < EMB; i += 256) c += (key[i] >= mid) ? 1 : 0;
#pragma unroll
        for (int off = 16; off; off >>= 1) c += __shfl_xor_sync(0xffffffffu, c, off);
        if ((tid & 31) == 0) atomicAdd(&cnt, c);
        __syncthreads();
        if (cnt >= KTOP) lo = mid; else hi = mid - 1u;
        __syncthreads();                    // all reads of cnt done before next reset
    }
    const unsigned thr = lo;                // 512th-largest key

    for (int i = tid; i < EMB; i += 256) {
        float xp = (key[i] >= thr) ? row[i] : 0.0f;
        int h = i >> 6, d = i & 63, j = (i & 63) >> 1;
        float outv;
        if (sel == 2) {
            outv = xp;                      // v: prune only
        } else {
            int ip = i ^ 1;
            float xo = (key[ip] >= thr) ? row[ip] : 0.0f;
            float ss, cs;
            if (sel == 0) { ss = g_sinq[t][j]; cs = g_cosq[t][j]; }
            else          { ss = g_sink[t][j]; cs = g_cosk[t][j]; }
            // out[2j] = x[2j]*cos - x[2j+1]*sin ; out[2j+1] = x[2j+1]*cos + x[2j]*sin
            float rot = (d & 1) ? xo : -xo;
            outv = fmaf(xp, cs, rot * ss);
        }
        g_qkvh[sel][b * HEADS + h][t][d] = outv;
    }
}

// ---------------- row softmax + fp16 round, writes attn_weights output ------------------
// grid = BH*T rows; w layout in d_out: (H, B, T, T) as fp32 values of fp16-rounded probs.
__global__ __launch_bounds__(256)
void softmax_kernel(const float* __restrict__ S, float* __restrict__ Wout)
{
    const long rowid = blockIdx.x;
    const int bh = (int)(rowid >> 11);
    const int t  = (int)(rowid & (TSEQ - 1));
    const int b  = bh >> 4, h = bh & 15;
    const float* src = S + (size_t)rowid * TSEQ;
    float* dst = Wout + (((size_t)(h * BATCH + b) * TSEQ + t) * TSEQ);

    const int tid = threadIdx.x;
    const int lane = tid & 31, wid = tid >> 5;
    __shared__ float red[8];

    float v[8];
    float m = -3.402823466e38f;
#pragma unroll
    for (int i = 0; i < 8; i++) { v[i] = src[tid + i * 256]; m = fmaxf(m, v[i]); }
#pragma unroll
    for (int off = 16; off; off >>= 1) m = fmaxf(m, __shfl_xor_sync(0xffffffffu, m, off));
    if (lane == 0) red[wid] = m;
    __syncthreads();
    float mx = red[0];
#pragma unroll
    for (int i = 1; i < 8; i++) mx = fmaxf(mx, red[i]);
    __syncthreads();

    float sum = 0.0f;
#pragma unroll
    for (int i = 0; i < 8; i++) { v[i] = expf(v[i] - mx); sum += v[i]; }
#pragma unroll
    for (int off = 16; off; off >>= 1) sum += __shfl_xor_sync(0xffffffffu, sum, off);
    if (lane == 0) red[wid] = sum;
    __syncthreads();
    float tot = 0.0f;
#pragma unroll
    for (int i = 0; i < 8; i++) tot += red[i];
    const float inv = 1.0f / tot;
#pragma unroll
    for (int i = 0; i < 8; i++) {
        float p = v[i] * inv;
        dst[tid + i * 256] = __half2float(__float2half_rn(p));  // exact ref fp16 round-trip
    }
}

// ---------------- PV: attn[t,d] = sum_s w[t,s] * v[s,d] ---------------------------------
// Reads the fp16-rounded probs straight back from d_out. BM=128 rows, BN=64 (=D), BK=8.
__global__ __launch_bounds__(256)
void pv_kernel(const float* __restrict__ Wfull)
{
    const int bh = blockIdx.z;
    const int b = bh >> 4, h = bh & 15;
    const float* A = Wfull + (size_t)(h * BATCH + b) * TSEQ * TSEQ;  // [T][T]
    const float* V = &g_qkvh[2][bh][0][0];                            // [T][64]

    __shared__ float As[8][128];
    __shared__ float Bs[8][64];
    const int tid = threadIdx.x;
    const int loadRow = tid >> 1;
    const int loadCol = (tid & 1) * 4;
    const float* Ap = A + (size_t)(blockIdx.y * 128 + loadRow) * TSEQ + loadCol;

    const int tx = tid & 15;   // n (d), TN=4
    const int ty = tid >> 4;   // m (t), TM=8

    float acc[8][4];
#pragma unroll
    for (int i = 0; i < 8; i++)
#pragma unroll
        for (int j = 0; j < 4; j++) acc[i][j] = 0.0f;

    for (int k0 = 0; k0 < TSEQ; k0 += 8) {
        float4 a = *(const float4*)(Ap + k0);
        As[loadCol + 0][loadRow] = a.x;
        As[loadCol + 1][loadRow] = a.y;
        As[loadCol + 2][loadRow] = a.z;
        As[loadCol + 3][loadRow] = a.w;
        if (tid < 128) {
            int r = tid >> 4, c4 = (tid & 15) * 4;   // 8 rows x 16 col-groups
            *(float4*)&Bs[r][c4] = *(const float4*)(V + (size_t)(k0 + r) * HDIM + c4);
        }
        __syncthreads();
#pragma unroll
        for (int kk = 0; kk < 8; kk++) {
            __align__(16) float ar[8];
            *(float4*)&ar[0] = *(const float4*)&As[kk][ty * 8];
            *(float4*)&ar[4] = *(const float4*)&As[kk][ty * 8 + 4];
            float4 br = *(const float4*)&Bs[kk][tx * 4];
#pragma unroll
            for (int i = 0; i < 8; i++) {
                acc[i][0] = fmaf(ar[i], br.x, acc[i][0]);
                acc[i][1] = fmaf(ar[i], br.y, acc[i][1]);
                acc[i][2] = fmaf(ar[i], br.z, acc[i][2]);
                acc[i][3] = fmaf(ar[i], br.w, acc[i][3]);
            }
        }
        __syncthreads();
    }

    const int t0 = blockIdx.y * 128 + ty * 8;
#pragma unroll
    for (int i = 0; i < 8; i++) {
        int n = b * TSEQ + (t0 + i);
        float4 o = make_float4(acc[i][0], acc[i][1], acc[i][2], acc[i][3]);
        *(float4*)&g_attn[n][h * HDIM + tx * 4] = o;
    }
}

// ---------------- launch ----------------------------------------------------------------
extern "C" void kernel_launch(void* const* d_in, const int* in_sizes, int n_in,
                              void* d_out, int out_size)
{
    (void)in_sizes; (void)n_in; (void)out_size;
    const float* query = (const float*)d_in[0];
    const float* keyx  = (const float*)d_in[1];
    const float* value = (const float*)d_in[2];
    const float* Wq = (const float*)d_in[3];
    const float* bq = (const float*)d_in[4];
    const float* Wk = (const float*)d_in[5];
    const float* bk = (const float*)d_in[6];
    const float* Wv = (const float*)d_in[7];
    const float* bv = (const float*)d_in[8];
    const float* Wo = (const float*)d_in[9];
    const float* bo = (const float*)d_in[10];

    float* out  = (float*)d_out;                         // (B,T,E) fp32
    float* wout = out + (size_t)NROWS * EMB;             // (H,B,T,T) fp32(fp16-rounded)

    float *proj, *qkvh, *scores, *attn;
    cudaGetSymbolAddress((void**)&proj,   g_proj);
    cudaGetSymbolAddress((void**)&qkvh,   g_qkvh);
    cudaGetSymbolAddress((void**)&scores, g_scores);
    cudaGetSymbolAddress((void**)&attn,   g_attn);

    // 1. xpos tables
    xpos_table_kernel<<<TSEQ, 32>>>();

    // 2. QKV projections: X(4096x1024) @ W^T(1024x1024) + b
    dim3 gproj(EMB / 128, NROWS / 128, 1);
    sgemm_nt<<<gproj, 256>>>(query, Wq, bq, proj,                               NROWS, EMB, EMB, 0, 0, 0);
    sgemm_nt<<<gproj, 256>>>(keyx,  Wk, bk, proj + (size_t)NROWS * EMB,         NROWS, EMB, EMB, 0, 0, 0);
    sgemm_nt<<<gproj, 256>>>(value, Wv, bv, proj + (size_t)2 * NROWS * EMB,     NROWS, EMB, EMB, 0, 0, 0);

    // 3. prune (exact top-512) + xpos + split heads
    prune_xpos_kernel<<<dim3(NROWS, 3), 256>>>();

    // 4. scores: per-head Q(2048x64) @ K^T  -> g_scores
    const long TD = (long)TSEQ * HDIM;
    const long TT = (long)TSEQ * TSEQ;
    sgemm_nt<<<dim3(TSEQ / 128, TSEQ / 128, BHX), 256>>>(
        qkvh, qkvh + (size_t)BHX * TD, nullptr, scores,
        TSEQ, TSEQ, HDIM, TD, TD, TT);

    // 5. softmax + fp16 round -> attn_weights output (H,B,T,T)
    softmax_kernel<<<BHX * TSEQ, 256>>>(scores, wout);

    // 6. PV (reads fp16-rounded probs from d_out) -> merged (B,T,E)
    pv_kernel<<<dim3(1, TSEQ / 128, BHX), 256>>>(wout);

    // 7. output projection -> out
    sgemm_nt<<<gproj, 256>>>(attn, Wo, bo, out, NROWS, EMB, EMB, 0, 0, 0);
}

// round 14
// speedup vs baseline: 1.6368x; 1.6368x over previous
#include <cuda_runtime.h>
#include <cuda_fp16.h>
#include <stdint.h>
#include <math.h>

// ---------------- problem constants ----------------
#define TSEQ   2048
#define BATCH  2
#define EMB    1024
#define HEADS  16
#define HDIM   64
#define BHX    (BATCH*HEADS)     // 32
#define NROWS  (BATCH*TSEQ)      // 4096
#define KTOP   512               // top 50% of 1024

// ---------------- scratch (device globals, no allocation) ----------------
__device__ float g_proj[3][NROWS][EMB];                       // QKV projection outputs
__device__ float g_qkvh[2][BHX][TSEQ][HDIM];                  // pruned+rotated q,k split-head
__device__ float g_vT[BHX][HDIM][TSEQ];                       // pruned v, TRANSPOSED per head
__device__ float g_scores[BHX][TSEQ][TSEQ];                   // raw attention scores
__device__ float g_attn[NROWS][EMB];                          // PV output, merged heads
__device__ float g_sinq[TSEQ][32], g_cosq[TSEQ][32];
__device__ float g_sink[TSEQ][32], g_cosk[TSEQ][32];

// ---------------- xpos tables ----------------
__global__ void xpos_table_kernel() {
    int t = blockIdx.x;
    int j = threadIdx.x;
    float basef = (2.0f * (float)j + 0.4f * 64.0f) / (1.4f * 64.0f);
    double power = ((double)t - 1024.0) / 512.0;
    double scale = pow((double)basef, power);
    float invff = (float)(1.0 / pow(10000.0, (double)j / 32.0));
    float angf  = (float)t * invff;                  // fp32 rounding matches reference
    double s = sin((double)angf);
    double c = cos((double)angf);
    g_sinq[t][j] = (float)(s * scale);
    g_cosq[t][j] = (float)(c * scale);
    g_sink[t][j] = (float)(s / scale);
    g_cosk[t][j] = (float)(c / scale);
}

// ---------------- tf32 tensor-core helpers ----------------
__device__ __forceinline__ void cp_async16(uint32_t dst, const void* src) {
    asm volatile("cp.async.cg.shared.global [%0], [%1], 16;\n" :: "r"(dst), "l"(src));
}
__device__ __forceinline__ void cp_commit() {
    asm volatile("cp.async.commit_group;\n" ::: "memory");
}
template<int N> __device__ __forceinline__ void cp_wait() {
    asm volatile("cp.async.wait_group %0;\n" :: "n"(N) : "memory");
}
__device__ __forceinline__ uint32_t f2tf(float x) {
    uint32_t u; asm("cvt.rna.tf32.f32 %0, %1;" : "=r"(u) : "f"(x)); return u;
}
__device__ __forceinline__ uint32_t tf_lo(float x, uint32_t hi) {
    return f2tf(x - __uint_as_float(hi));
}
__device__ __forceinline__ void mma_tf32(float* c, const uint32_t* a, const uint32_t* b) {
    asm volatile(
        "mma.sync.aligned.m16n8k8.row.col.f32.tf32.tf32.f32 "
        "{%0,%1,%2,%3},{%4,%5,%6,%7},{%8,%9},{%0,%1,%2,%3};"
        : "+f"(c[0]), "+f"(c[1]), "+f"(c[2]), "+f"(c[3])
        : "r"(a[0]), "r"(a[1]), "r"(a[2]), "r"(a[3]), "r"(b[0]), "r"(b[1]));
}

// ---------------- 3xTF32 GEMM: C[m,n] = sum_k A[m,k]*B[n,k] (+bias[n]) -------------
// A: M x K row-major, B: N x K row-major. BK=16, double-buffered cp.async.
// Error-compensated: acc += a_hi*b_lo + a_lo*b_hi + a_hi*b_hi  (~fp32 accuracy).
// SPLIT_A/SPLIT_B select which operands need the lo correction term.
#define BK   16
#define SPAD 20

template<int BM, int BN, int NWM, int NWN, bool SPLIT_A, bool SPLIT_B, bool PVMODE>
__global__ void __launch_bounds__(32*NWM*NWN)
tf32_gemm(const float* __restrict__ A, const float* __restrict__ B,
          const float* __restrict__ bias, float* __restrict__ C,
          int K, int ldc, long strideA, long strideB, long strideC)
{
    constexpr int THREADS = 32 * NWM * NWN;
    constexpr int WM = BM / NWM;
    constexpr int WN = BN / NWN;
    constexpr int MT = WM / 16;
    constexpr int NT = WN / 8;

    __shared__ float sA[2][BM][SPAD];
    __shared__ float sB[2][BN][SPAD];

    const int z = blockIdx.z;
    if (PVMODE) {
        // z = b*16 + h ; A = w in (H,B,T,T); B = vT[bh]; C = attn merged (B,T,E)
        int b = z >> 4, h = z & 15;
        A += (size_t)(h * BATCH + b) * TSEQ * TSEQ;
        B += (size_t)z * HDIM * TSEQ;
        C += (size_t)b * TSEQ * EMB + (size_t)h * HDIM;
    } else {
        A += (size_t)z * strideA;
        B += (size_t)z * strideB;
        C += (size_t)z * strideC;
    }
    const int m0 = blockIdx.y * BM;
    const int n0 = blockIdx.x * BN;

    const int tid = threadIdx.x;
    const int lane = tid & 31, wid = tid >> 5;
    const int wm = wid % NWM, wn = wid / NWM;

    float acc[MT][NT][4];
#pragma unroll
    for (int i = 0; i < MT; i++)
#pragma unroll
        for (int j = 0; j < NT; j++)
#pragma unroll
            for (int r = 0; r < 4; r++) acc[i][j][r] = 0.0f;

    auto load_stage = [&](int buf, int k0) {
#pragma unroll
        for (int idx = tid; idx < BM * 4; idx += THREADS) {
            int m = idx >> 2, c = (idx & 3) * 4;
            cp_async16((uint32_t)__cvta_generic_to_shared(&sA[buf][m][c]),
                       A + (size_t)(m0 + m) * K + k0 + c);
        }
#pragma unroll
        for (int idx = tid; idx < BN * 4; idx += THREADS) {
            int n = idx >> 2, c = (idx & 3) * 4;
            cp_async16((uint32_t)__cvta_generic_to_shared(&sB[buf][n][c]),
                       B + (size_t)(n0 + n) * K + k0 + c);
        }
        cp_commit();
    };

    const int ntiles = K / BK;
    load_stage(0, 0);

    for (int it = 0; it < ntiles; it++) {
        if (it + 1 < ntiles) { load_stage((it + 1) & 1, (it + 1) * BK); cp_wait<1>(); }
        else                 { cp_wait<0>(); }
        __syncthreads();
        const float (*cA)[SPAD] = sA[it & 1];
        const float (*cB)[SPAD] = sB[it & 1];
#pragma unroll
        for (int kk = 0; kk < 2; kk++) {
            const int kc = kk * 8 + (lane & 3);
            uint32_t af[MT][4], al[MT][4];
#pragma unroll
            for (int mt = 0; mt < MT; mt++) {
                int m = wm * WM + mt * 16 + (lane >> 2);
                float x0 = cA[m][kc],     x1 = cA[m + 8][kc];
                float x2 = cA[m][kc + 4], x3 = cA[m + 8][kc + 4];
                af[mt][0] = f2tf(x0); af[mt][1] = f2tf(x1);
                af[mt][2] = f2tf(x2); af[mt][3] = f2tf(x3);
                if (SPLIT_A) {
                    al[mt][0] = tf_lo(x0, af[mt][0]); al[mt][1] = tf_lo(x1, af[mt][1]);
                    al[mt][2] = tf_lo(x2, af[mt][2]); al[mt][3] = tf_lo(x3, af[mt][3]);
                }
            }
            uint32_t bf[NT][2], bl[NT][2];
#pragma unroll
            for (int nt = 0; nt < NT; nt++) {
                int n = wn * WN + nt * 8 + (lane >> 2);
                float y0 = cB[n][kc], y1 = cB[n][kc + 4];
                bf[nt][0] = f2tf(y0); bf[nt][1] = f2tf(y1);
                if (SPLIT_B) {
                    bl[nt][0] = tf_lo(y0, bf[nt][0]); bl[nt][1] = tf_lo(y1, bf[nt][1]);
                }
            }
#pragma unroll
            for (int mt = 0; mt < MT; mt++)
#pragma unroll
                for (int nt = 0; nt < NT; nt++) {
                    if (SPLIT_B) mma_tf32(acc[mt][nt], af[mt], bl[nt]);
                    if (SPLIT_A) mma_tf32(acc[mt][nt], al[mt], bf[nt]);
                    mma_tf32(acc[mt][nt], af[mt], bf[nt]);
                }
        }
        __syncthreads();
    }

    // epilogue
#pragma unroll
    for (int mt = 0; mt < MT; mt++) {
        int r0 = m0 + wm * WM + mt * 16 + (lane >> 2);
#pragma unroll
        for (int nt = 0; nt < NT; nt++) {
            int c0 = n0 + wn * WN + nt * 8 + (lane & 3) * 2;
            float b0 = 0.0f, b1 = 0.0f;
            if (bias) { b0 = bias[c0]; b1 = bias[c0 + 1]; }
            float2 v0 = make_float2(acc[mt][nt][0] + b0, acc[mt][nt][1] + b1);
            float2 v1 = make_float2(acc[mt][nt][2] + b0, acc[mt][nt][3] + b1);
            *(float2*)&C[(size_t)r0 * ldc + c0]       = v0;
            *(float2*)&C[(size_t)(r0 + 8) * ldc + c0] = v1;
        }
    }
}

// ---------------- pruning (exact top-512) + xpos + split-heads ----------------
__global__ __launch_bounds__(256)
void prune_xpos_kernel() {
    const int n   = blockIdx.x;
    const int sel = blockIdx.y;        // 0=q, 1=k, 2=v
    const int b   = n >> 11;
    const int t   = n & (TSEQ - 1);
    const int tid = threadIdx.x;

    __shared__ float    row[EMB];
    __shared__ unsigned key[EMB];
    __shared__ int      cnt;

    const float scl = (sel == 0) ? 0.125f : 1.0f;
#pragma unroll
    for (int i = tid; i < EMB; i += 256) {
        float x = g_proj[sel][n][i] * scl;
        row[i] = x;
        unsigned u = __float_as_uint(x);
        key[i] = (u & 0x80000000u) ? ~u : (u | 0x80000000u);
    }
    __syncthreads();

    unsigned lo = 0u, hi = 0xFFFFFFFFu;
    while (lo < hi) {
        unsigned mid = lo + ((hi - lo) >> 1) + 1u;
        if (tid == 0) cnt = 0;
        __syncthreads();
        int c = 0;
        for (int i = tid; i < EMB; i += 256) c += (key[i] >= mid) ? 1 : 0;
#pragma unroll
        for (int off = 16; off; off >>= 1) c += __shfl_xor_sync(0xffffffffu, c, off);
        if ((tid & 31) == 0) atomicAdd(&cnt, c);
        __syncthreads();
        if (cnt >= KTOP) lo = mid; else hi = mid - 1u;
        __syncthreads();
    }
    const unsigned thr = lo;

    for (int i = tid; i < EMB; i += 256) {
        float xp = (key[i] >= thr) ? row[i] : 0.0f;
        int h = i >> 6, d = i & 63, j = (i & 63) >> 1;
        if (sel == 2) {
            g_vT[b * HEADS + h][d][t] = xp;       // transposed V for tensor-core PV
        } else {
            int ip = i ^ 1;
            float xo = (key[ip] >= thr) ? row[ip] : 0.0f;
            float ss, cs;
            if (sel == 0) { ss = g_sinq[t][j]; cs = g_cosq[t][j]; }
            else          { ss = g_sink[t][j]; cs = g_cosk[t][j]; }
            float rot = (d & 1) ? xo : -xo;
            g_qkvh[sel][b * HEADS + h][t][d] = fmaf(xp, cs, rot * ss);
        }
    }
}

// ---------------- row softmax + fp16 round -> attn_weights output ------------------
__global__ __launch_bounds__(256)
void softmax_kernel(const float* __restrict__ S, float* __restrict__ Wout)
{
    const long rowid = blockIdx.x;
    const int bh = (int)(rowid >> 11);
    const int t  = (int)(rowid & (TSEQ - 1));
    const int b  = bh >> 4, h = bh & 15;
    const float* src = S + (size_t)rowid * TSEQ;
    float* dst = Wout + (((size_t)(h * BATCH + b) * TSEQ + t) * TSEQ);

    const int tid = threadIdx.x;
    const int lane = tid & 31, wid = tid >> 5;
    __shared__ float red[8];

    float v[8];
    float m = -3.402823466e38f;
#pragma unroll
    for (int i = 0; i < 8; i++) { v[i] = src[tid + i * 256]; m = fmaxf(m, v[i]); }
#pragma unroll
    for (int off = 16; off; off >>= 1) m = fmaxf(m, __shfl_xor_sync(0xffffffffu, m, off));
    if (lane == 0) red[wid] = m;
    __syncthreads();
    float mx = red[0];
#pragma unroll
    for (int i = 1; i < 8; i++) mx = fmaxf(mx, red[i]);
    __syncthreads();

    float sum = 0.0f;
#pragma unroll
    for (int i = 0; i < 8; i++) { v[i] = expf(v[i] - mx); sum += v[i]; }
#pragma unroll
    for (int off = 16; off; off >>= 1) sum += __shfl_xor_sync(0xffffffffu, sum, off);
    if (lane == 0) red[wid] = sum;
    __syncthreads();
    float tot = 0.0f;
#pragma unroll
    for (int i = 0; i < 8; i++) tot += red[i];
    const float inv = 1.0f / tot;
#pragma unroll
    for (int i = 0; i < 8; i++) {
        float p = v[i] * inv;
        dst[tid + i * 256] = __half2float(__float2half_rn(p));
    }
}

// ---------------- launch ----------------------------------------------------------------
extern "C" void kernel_launch(void* const* d_in, const int* in_sizes, int n_in,
                              void* d_out, int out_size)
{
    (void)in_sizes; (void)n_in; (void)out_size;
    const float* query = (const float*)d_in[0];
    const float* keyx  = (const float*)d_in[1];
    const float* value = (const float*)d_in[2];
    const float* Wq = (const float*)d_in[3];
    const float* bq = (const float*)d_in[4];
    const float* Wk = (const float*)d_in[5];
    const float* bk = (const float*)d_in[6];
    const float* Wv = (const float*)d_in[7];
    const float* bv = (const float*)d_in[8];
    const float* Wo = (const float*)d_in[9];
    const float* bo = (const float*)d_in[10];

    float* out  = (float*)d_out;                 // (B,T,E) fp32
    float* wout = out + (size_t)NROWS * EMB;     // (H,B,T,T) fp32(fp16-rounded)

    float *proj, *qkvh, *vT, *scores, *attn;
    cudaGetSymbolAddress((void**)&proj,   g_proj);
    cudaGetSymbolAddress((void**)&qkvh,   g_qkvh);
    cudaGetSymbolAddress((void**)&vT,     g_vT);
    cudaGetSymbolAddress((void**)&scores, g_scores);
    cudaGetSymbolAddress((void**)&attn,   g_attn);

    // 1. xpos tables
    xpos_table_kernel<<<TSEQ, 32>>>();

    // 2. QKV projections: X(4096x1024) @ W^T + b   (3xTF32 tensor cores)
    dim3 gproj(EMB / 128, NROWS / 128, 1);
    tf32_gemm<128,128,2,4,true,true,false><<<gproj, 256>>>(query, Wq, bq, proj,
        EMB, EMB, 0, 0, 0);
    tf32_gemm<128,128,2,4,true,true,false><<<gproj, 256>>>(keyx,  Wk, bk, proj + (size_t)NROWS * EMB,
        EMB, EMB, 0, 0, 0);
    tf32_gemm<128,128,2,4,true,true,false><<<gproj, 256>>>(value, Wv, bv, proj + (size_t)2 * NROWS * EMB,
        EMB, EMB, 0, 0, 0);

    // 3. prune (exact top-512) + xpos + split heads (+ V transpose)
    prune_xpos_kernel<<<dim3(NROWS, 3), 256>>>();

    // 4. scores: per-head Q(2048x64) @ K^T -> g_scores  (3xTF32)
    const long TD = (long)TSEQ * HDIM;
    const long TT = (long)TSEQ * TSEQ;
    tf32_gemm<128,128,2,4,true,true,false><<<dim3(TSEQ/128, TSEQ/128, BHX), 256>>>(
        qkvh, qkvh + (size_t)BHX * TD, nullptr, scores,
        HDIM, TSEQ, TD, TD, TT);

    // 5. softmax + fp16 round -> attn_weights output (H,B,T,T)
    softmax_kernel<<<BHX * TSEQ, 256>>>(scores, wout);

    // 6. PV: w fp16-exact in tf32 (no A split) @ vT^T (B split) -> merged (B,T,E)
    tf32_gemm<128,64,2,2,false,true,true><<<dim3(1, TSEQ/128, BHX), 128>>>(
        wout, vT, nullptr, attn,
        TSEQ, EMB, 0, 0, 0);

    // 7. output projection -> out  (3xTF32)
    tf32_gemm<128,128,2,4,true,true,false><<<gproj, 256>>>(attn, Wo, bo, out,
        EMB, EMB, 0, 0, 0);
}

// round 15
// speedup vs baseline: 1.6381x; 1.0008x over previous
#include <cuda_runtime.h>
#include <cuda_fp16.h>
#include <stdint.h>
#include <math.h>

// ---------------- problem constants ----------------
#define TSEQ   2048
#define BATCH  2
#define EMB    1024
#define HEADS  16
#define HDIM   64
#define BHX    (BATCH*HEADS)     // 32
#define NROWS  (BATCH*TSEQ)      // 4096
#define KTOP   512               // top 50% of 1024

// ---------------- scratch (device globals, no allocation) ----------------
__device__ float g_proj[3][NROWS][EMB];                       // QKV projection outputs
__device__ float g_qkvh[2][BHX][TSEQ][HDIM];                  // pruned+rotated q,k split-head
__device__ float g_vT[BHX][HDIM][TSEQ];                       // pruned v, TRANSPOSED per head
__device__ float g_scores[BHX][TSEQ][TSEQ];                   // raw attention scores
__device__ float g_attn[NROWS][EMB];                          // PV output, merged heads
__device__ float g_sinq[TSEQ][32], g_cosq[TSEQ][32];
__device__ float g_sink[TSEQ][32], g_cosk[TSEQ][32];

// ---------------- xpos tables ----------------
__global__ void xpos_table_kernel() {
    int t = blockIdx.x;
    int j = threadIdx.x;
    float basef = (2.0f * (float)j + 0.4f * 64.0f) / (1.4f * 64.0f);
    double power = ((double)t - 1024.0) / 512.0;
    double scale = pow((double)basef, power);
    float invff = (float)(1.0 / pow(10000.0, (double)j / 32.0));
    float angf  = (float)t * invff;                  // fp32 rounding matches reference
    double s = sin((double)angf);
    double c = cos((double)angf);
    g_sinq[t][j] = (float)(s * scale);
    g_cosq[t][j] = (float)(c * scale);
    g_sink[t][j] = (float)(s / scale);
    g_cosk[t][j] = (float)(c / scale);
}

// ---------------- tf32 tensor-core helpers ----------------
__device__ __forceinline__ void cp_async16(uint32_t dst, const void* src) {
    asm volatile("cp.async.cg.shared.global [%0], [%1], 16;\n" :: "r"(dst), "l"(src));
}
__device__ __forceinline__ void cp_commit() {
    asm volatile("cp.async.commit_group;\n" ::: "memory");
}
template<int N> __device__ __forceinline__ void cp_wait() {
    asm volatile("cp.async.wait_group %0;\n" :: "n"(N) : "memory");
}
__device__ __forceinline__ uint32_t f2tf(float x) {
    uint32_t u; asm("cvt.rna.tf32.f32 %0, %1;" : "=r"(u) : "f"(x)); return u;
}
__device__ __forceinline__ uint32_t tf_lo(float x, uint32_t hi) {
    return f2tf(x - __uint_as_float(hi));
}
__device__ __forceinline__ void mma_tf32(float* c, const uint32_t* a, const uint32_t* b) {
    asm volatile(
        "mma.sync.aligned.m16n8k8.row.col.f32.tf32.tf32.f32 "
        "{%0,%1,%2,%3},{%4,%5,%6,%7},{%8,%9},{%0,%1,%2,%3};"
        : "+f"(c[0]), "+f"(c[1]), "+f"(c[2]), "+f"(c[3])
        : "r"(a[0]), "r"(a[1]), "r"(a[2]), "r"(a[3]), "r"(b[0]), "r"(b[1]));
}

// ---------------- 3xTF32 GEMM: C[m,n] = sum_k A[m,k]*B[n,k] (+bias[n]) -------------
// A: M x K row-major, B: N x K row-major. BK=16, double-buffered cp.async.
// Error-compensated: acc += a_hi*b_lo + a_lo*b_hi + a_hi*b_hi  (~fp32 accuracy).
// SPLIT_A/SPLIT_B select which operands need the lo correction term.
#define BK   16
#define SPAD 20

template<int BM, int BN, int NWM, int NWN, bool SPLIT_A, bool SPLIT_B, bool PVMODE>
__global__ void __launch_bounds__(32*NWM*NWN)
tf32_gemm(const float* __restrict__ A, const float* __restrict__ B,
          const float* __restrict__ bias, float* __restrict__ C,
          int K, int ldc, long strideA, long strideB, long strideC)
{
    constexpr int THREADS = 32 * NWM * NWN;
    constexpr int WM = BM / NWM;
    constexpr int WN = BN / NWN;
    constexpr int MT = WM / 16;
    constexpr int NT = WN / 8;

    __shared__ float sA[2][BM][SPAD];
    __shared__ float sB[2][BN][SPAD];

    const int z = blockIdx.z;
    if (PVMODE) {
        // z = b*16 + h ; A = w in (H,B,T,T); B = vT[bh]; C = attn merged (B,T,E)
        int b = z >> 4, h = z & 15;
        A += (size_t)(h * BATCH + b) * TSEQ * TSEQ;
        B += (size_t)z * HDIM * TSEQ;
        C += (size_t)b * TSEQ * EMB + (size_t)h * HDIM;
    } else {
        A += (size_t)z * strideA;
        B += (size_t)z * strideB;
        C += (size_t)z * strideC;
    }
    const int m0 = blockIdx.y * BM;
    const int n0 = blockIdx.x * BN;

    const int tid = threadIdx.x;
    const int lane = tid & 31, wid = tid >> 5;
    const int wm = wid % NWM, wn = wid / NWM;

    float acc[MT][NT][4];
#pragma unroll
    for (int i = 0; i < MT; i++)
#pragma unroll
        for (int j = 0; j < NT; j++)
#pragma unroll
            for (int r = 0; r < 4; r++) acc[i][j][r] = 0.0f;

    auto load_stage = [&](int buf, int k0) {
#pragma unroll
        for (int idx = tid; idx < BM * 4; idx += THREADS) {
            int m = idx >> 2, c = (idx & 3) * 4;
            cp_async16((uint32_t)__cvta_generic_to_shared(&sA[buf][m][c]),
                       A + (size_t)(m0 + m) * K + k0 + c);
        }
#pragma unroll
        for (int idx = tid; idx < BN * 4; idx += THREADS) {
            int n = idx >> 2, c = (idx & 3) * 4;
            cp_async16((uint32_t)__cvta_generic_to_shared(&sB[buf][n][c]),
                       B + (size_t)(n0 + n) * K + k0 + c);
        }
        cp_commit();
    };

    const int ntiles = K / BK;
    load_stage(0, 0);

    for (int it = 0; it < ntiles; it++) {
        if (it + 1 < ntiles) { load_stage((it + 1) & 1, (it + 1) * BK); cp_wait<1>(); }
        else                 { cp_wait<0>(); }
        __syncthreads();
        const float (*cA)[SPAD] = sA[it & 1];
        const float (*cB)[SPAD] = sB[it & 1];
#pragma unroll
        for (int kk = 0; kk < 2; kk++) {
            const int kc = kk * 8 + (lane & 3);
            uint32_t af[MT][4], al[MT][4];
#pragma unroll
            for (int mt = 0; mt < MT; mt++) {
                int m = wm * WM + mt * 16 + (lane >> 2);
                float x0 = cA[m][kc],     x1 = cA[m + 8][kc];
                float x2 = cA[m][kc + 4], x3 = cA[m + 8][kc + 4];
                af[mt][0] = f2tf(x0); af[mt][1] = f2tf(x1);
                af[mt][2] = f2tf(x2); af[mt][3] = f2tf(x3);
                if (SPLIT_A) {
                    al[mt][0] = tf_lo(x0, af[mt][0]); al[mt][1] = tf_lo(x1, af[mt][1]);
                    al[mt][2] = tf_lo(x2, af[mt][2]); al[mt][3] = tf_lo(x3, af[mt][3]);
                }
            }
            uint32_t bf[NT][2], bl[NT][2];
#pragma unroll
            for (int nt = 0; nt < NT; nt++) {
                int n = wn * WN + nt * 8 + (lane >> 2);
                float y0 = cB[n][kc], y1 = cB[n][kc + 4];
                bf[nt][0] = f2tf(y0); bf[nt][1] = f2tf(y1);
                if (SPLIT_B) {
                    bl[nt][0] = tf_lo(y0, bf[nt][0]); bl[nt][1] = tf_lo(y1, bf[nt][1]);
                }
            }
#pragma unroll
            for (int mt = 0; mt < MT; mt++)
#pragma unroll
                for (int nt = 0; nt < NT; nt++) {
                    if (SPLIT_B) mma_tf32(acc[mt][nt], af[mt], bl[nt]);
                    if (SPLIT_A) mma_tf32(acc[mt][nt], al[mt], bf[nt]);
                    mma_tf32(acc[mt][nt], af[mt], bf[nt]);
                }
        }
        __syncthreads();
    }

    // epilogue
#pragma unroll
    for (int mt = 0; mt < MT; mt++) {
        int r0 = m0 + wm * WM + mt * 16 + (lane >> 2);
#pragma unroll
        for (int nt = 0; nt < NT; nt++) {
            int c0 = n0 + wn * WN + nt * 8 + (lane & 3) * 2;
            float b0 = 0.0f, b1 = 0.0f;
            if (bias) { b0 = bias[c0]; b1 = bias[c0 + 1]; }
            float2 v0 = make_float2(acc[mt][nt][0] + b0, acc[mt][nt][1] + b1);
            float2 v1 = make_float2(acc[mt][nt][2] + b0, acc[mt][nt][3] + b1);
            *(float2*)&C[(size_t)r0 * ldc + c0]       = v0;
            *(float2*)&C[(size_t)(r0 + 8) * ldc + c0] = v1;
        }
    }
}

// ---------------- pruning (exact top-512) + xpos + split-heads ----------------
__global__ __launch_bounds__(256)
void prune_xpos_kernel() {
    const int n   = blockIdx.x;
    const int sel = blockIdx.y;        // 0=q, 1=k, 2=v
    const int b   = n >> 11;
    const int t   = n & (TSEQ - 1);
    const int tid = threadIdx.x;

    __shared__ float    row[EMB];
    __shared__ unsigned key[EMB];
    __shared__ int      cnt;

    const float scl = (sel == 0) ? 0.125f : 1.0f;
#pragma unroll
    for (int i = tid; i < EMB; i += 256) {
        float x = g_proj[sel][n][i] * scl;
        row[i] = x;
        unsigned u = __float_as_uint(x);
        key[i] = (u & 0x80000000u) ? ~u : (u | 0x80000000u);
    }
    __syncthreads();

    unsigned lo = 0u, hi = 0xFFFFFFFFu;
    while (lo < hi) {
        unsigned mid = lo + ((hi - lo) >> 1) + 1u;
        if (tid == 0) cnt = 0;
        __syncthreads();
        int c = 0;
        for (int i = tid; i < EMB; i += 256) c += (key[i] >= mid) ? 1 : 0;
#pragma unroll
        for (int off = 16; off; off >>= 1) c += __shfl_xor_sync(0xffffffffu, c, off);
        if ((tid & 31) == 0) atomicAdd(&cnt, c);
        __syncthreads();
        if (cnt >= KTOP) lo = mid; else hi = mid - 1u;
        __syncthreads();
    }
    const unsigned thr = lo;

    for (int i = tid; i < EMB; i += 256) {
        float xp = (key[i] >= thr) ? row[i] : 0.0f;
        int h = i >> 6, d = i & 63, j = (i & 63) >> 1;
        if (sel == 2) {
            g_vT[b * HEADS + h][d][t] = xp;       // transposed V for tensor-core PV
        } else {
            int ip = i ^ 1;
            float xo = (key[ip] >= thr) ? row[ip] : 0.0f;
            float ss, cs;
            if (sel == 0) { ss = g_sinq[t][j]; cs = g_cosq[t][j]; }
            else          { ss = g_sink[t][j]; cs = g_cosk[t][j]; }
            float rot = (d & 1) ? xo : -xo;
            g_qkvh[sel][b * HEADS + h][t][d] = fmaf(xp, cs, rot * ss);
        }
    }
}

// ---------------- row softmax + fp16 round -> attn_weights output ------------------
__global__ __launch_bounds__(256)
void softmax_kernel(const float* __restrict__ S, float* __restrict__ Wout)
{
    const long rowid = blockIdx.x;
    const int bh = (int)(rowid >> 11);
    const int t  = (int)(rowid & (TSEQ - 1));
    const int b  = bh >> 4, h = bh & 15;
    const float* src = S + (size_t)rowid * TSEQ;
    float* dst = Wout + (((size_t)(h * BATCH + b) * TSEQ + t) * TSEQ);

    const int tid = threadIdx.x;
    const int lane = tid & 31, wid = tid >> 5;
    __shared__ float red[8];

    float v[8];
    float m = -3.402823466e38f;
#pragma unroll
    for (int i = 0; i < 8; i++) { v[i] = src[tid + i * 256]; m = fmaxf(m, v[i]); }
#pragma unroll
    for (int off = 16; off; off >>= 1) m = fmaxf(m, __shfl_xor_sync(0xffffffffu, m, off));
    if (lane == 0) red[wid] = m;
    __syncthreads();
    float mx = red[0];
#pragma unroll
    for (int i = 1; i < 8; i++) mx = fmaxf(mx, red[i]);
    __syncthreads();

    float sum = 0.0f;
#pragma unroll
    for (int i = 0; i < 8; i++) { v[i] = expf(v[i] - mx); sum += v[i]; }
#pragma unroll
    for (int off = 16; off; off >>= 1) sum += __shfl_xor_sync(0xffffffffu, sum, off);
    if (lane == 0) red[wid] = sum;
    __syncthreads();
    float tot = 0.0f;
#pragma unroll
    for (int i = 0; i < 8; i++) tot += red[i];
    const float inv = 1.0f / tot;
#pragma unroll
    for (int i = 0; i < 8; i++) {
        float p = v[i] * inv;
        dst[tid + i * 256] = __half2float(__float2half_rn(p));
    }
}

// ---------------- launch ----------------------------------------------------------------
extern "C" void kernel_launch(void* const* d_in, const int* in_sizes, int n_in,
                              void* d_out, int out_size)
{
    (void)in_sizes; (void)n_in; (void)out_size;
    const float* query = (const float*)d_in[0];
    const float* keyx  = (const float*)d_in[1];
    const float* value = (const float*)d_in[2];
    const float* Wq = (const float*)d_in[3];
    const float* bq = (const float*)d_in[4];
    const float* Wk = (const float*)d_in[5];
    const float* bk = (const float*)d_in[6];
    const float* Wv = (const float*)d_in[7];
    const float* bv = (const float*)d_in[8];
    const float* Wo = (const float*)d_in[9];
    const float* bo = (const float*)d_in[10];

    float* out  = (float*)d_out;                 // (B,T,E) fp32
    float* wout = out + (size_t)NROWS * EMB;     // (H,B,T,T) fp32(fp16-rounded)

    float *proj, *qkvh, *vT, *scores, *attn;
    cudaGetSymbolAddress((void**)&proj,   g_proj);
    cudaGetSymbolAddress((void**)&qkvh,   g_qkvh);
    cudaGetSymbolAddress((void**)&vT,     g_vT);
    cudaGetSymbolAddress((void**)&scores, g_scores);
    cudaGetSymbolAddress((void**)&attn,   g_attn);

    // 1. xpos tables
    xpos_table_kernel<<<TSEQ, 32>>>();

    // 2. QKV projections: X(4096x1024) @ W^T + b   (3xTF32 tensor cores)
    dim3 gproj(EMB / 128, NROWS / 128, 1);
    tf32_gemm<128,128,2,4,true,true,false><<<gproj, 256>>>(query, Wq, bq, proj,
        EMB, EMB, 0, 0, 0);
    tf32_gemm<128,128,2,4,true,true,false><<<gproj, 256>>>(keyx,  Wk, bk, proj + (size_t)NROWS * EMB,
        EMB, EMB, 0, 0, 0);
    tf32_gemm<128,128,2,4,true,true,false><<<gproj, 256>>>(value, Wv, bv, proj + (size_t)2 * NROWS * EMB,
        EMB, EMB, 0, 0, 0);

    // 3. prune (exact top-512) + xpos + split heads (+ V transpose)
    prune_xpos_kernel<<<dim3(NROWS, 3), 256>>>();

    // 4. scores: per-head Q(2048x64) @ K^T -> g_scores  (3xTF32)
    const long TD = (long)TSEQ * HDIM;
    const long TT = (long)TSEQ * TSEQ;
    tf32_gemm<128,128,2,4,true,true,false><<<dim3(TSEQ/128, TSEQ/128, BHX), 256>>>(
        qkvh, qkvh + (size_t)BHX * TD, nullptr, scores,
        HDIM, TSEQ, TD, TD, TT);

    // 5. softmax + fp16 round -> attn_weights output (H,B,T,T)
    softmax_kernel<<<BHX * TSEQ, 256>>>(scores, wout);

    // 6. PV: w fp16-exact in tf32 (no A split) @ vT^T (B split) -> merged (B,T,E)
    tf32_gemm<128,64,2,2,false,true,true><<<dim3(1, TSEQ/128, BHX), 128>>>(
        wout, vT, nullptr, attn,
        TSEQ, EMB, 0, 0, 0);

    // 7. output projection -> out  (3xTF32)
    tf32_gemm<128,128,2,4,true,true,false><<<gproj, 256>>>(attn, Wo, bo, out,
        EMB, EMB, 0, 0, 0);
}

// round 16
// speedup vs baseline: 1.9851x; 1.2118x over previous
#include <cuda_runtime.h>
#include <cuda_fp16.h>
#include <cuda_bf16.h>
#include <stdint.h>
#include <math.h>

// ---------------- problem constants ----------------
#define TSEQ   2048
#define BATCH  2
#define EMB    1024
#define HEADS  16
#define HDIM   64
#define BHX    (BATCH*HEADS)     // 32
#define NROWS  (BATCH*TSEQ)      // 4096
#define KTOP   512               // top 50% of 1024

// ---------------- scratch (device globals, no allocation) ----------------
__device__ float g_proj[3][NROWS][EMB];                       // QKV projection outputs
__device__ float g_qkvh[2][BHX][TSEQ][HDIM];                  // pruned+rotated q,k split-head
__device__ float g_vT[BHX][HDIM][TSEQ];                       // pruned v, TRANSPOSED per head
__device__ float g_scores[BHX][TSEQ][TSEQ];                   // raw attention scores
__device__ float g_attn[NROWS][EMB];                          // PV output, merged heads
__device__ float g_sinq[TSEQ][32], g_cosq[TSEQ][32];
__device__ float g_sink[TSEQ][32], g_cosk[TSEQ][32];

// ---------------- xpos tables ----------------
__global__ void xpos_table_kernel() {
    int t = blockIdx.x;
    int j = threadIdx.x;
    float basef = (2.0f * (float)j + 0.4f * 64.0f) / (1.4f * 64.0f);
    double power = ((double)t - 1024.0) / 512.0;
    double scale = pow((double)basef, power);
    float invff = (float)(1.0 / pow(10000.0, (double)j / 32.0));
    float angf  = (float)t * invff;                  // fp32 rounding matches reference
    double s = sin((double)angf);
    double c = cos((double)angf);
    g_sinq[t][j] = (float)(s * scale);
    g_cosq[t][j] = (float)(c * scale);
    g_sink[t][j] = (float)(s / scale);
    g_cosk[t][j] = (float)(c / scale);
}

// ---------------- bf16 split helpers ----------------
// cvt.rn.bf16x2.f32 d, a, b  packs a -> UPPER 16 bits, b -> LOWER 16 bits.
__device__ __forceinline__ uint32_t bfpack(float up, float lo) {
    uint32_t r;
    asm("cvt.rn.bf16x2.f32 %0, %1, %2;" : "=r"(r) : "f"(up), "f"(lo));
    return r;
}
__device__ __forceinline__ float bf_lo_f(uint32_t h) { return __uint_as_float(h << 16); }
__device__ __forceinline__ float bf_up_f(uint32_t h) { return __uint_as_float(h & 0xffff0000u); }

// convert 8 consecutive floats -> packed bf16 hi plane (uint4) + lo plane (uint4)
__device__ __forceinline__ void cvt8(const float4& x0, const float4& x1,
                                     uint4& h, uint4& l) {
    h.x = bfpack(x0.y, x0.x);
    h.y = bfpack(x0.w, x0.z);
    h.z = bfpack(x1.y, x1.x);
    h.w = bfpack(x1.w, x1.z);
    l.x = bfpack(x0.y - bf_up_f(h.x), x0.x - bf_lo_f(h.x));
    l.y = bfpack(x0.w - bf_up_f(h.y), x0.z - bf_lo_f(h.y));
    l.z = bfpack(x1.y - bf_up_f(h.z), x1.x - bf_lo_f(h.z));
    l.w = bfpack(x1.w - bf_up_f(h.w), x1.z - bf_lo_f(h.w));
}

__device__ __forceinline__ void mma_bf16(float* c, const uint32_t* a, const uint32_t* b) {
    asm volatile(
        "mma.sync.aligned.m16n8k16.row.col.f32.bf16.bf16.f32 "
        "{%0,%1,%2,%3},{%4,%5,%6,%7},{%8,%9},{%0,%1,%2,%3};"
        : "+f"(c[0]), "+f"(c[1]), "+f"(c[2]), "+f"(c[3])
        : "r"(a[0]), "r"(a[1]), "r"(a[2]), "r"(a[3]), "r"(b[0]), "r"(b[1]));
}

// ---------------- 3xBF16 GEMM: C[m,n] = sum_k A[m,k]*B[n,k] (+bias[n]) -------------
// A: M x K row-major, B: N x K row-major (both fp32 in gmem).
// Operands split once during LDG->STS into bf16 hi/lo smem planes (SPH=24 pad,
// conflict-free). Mainloop: pure LDS + mma (a_hi*b_lo + a_lo*b_hi + a_hi*b_hi).
// BK=16 = one m16n8k16 step, register-staged double buffer, 1 sync per tile.
#define BK   16
#define SPH  24

template<int BM, int BN, int NWM, int NWN, bool PVMODE>
__global__ void __launch_bounds__(32*NWM*NWN)
bf16_gemm(const float* __restrict__ A, const float* __restrict__ B,
          const float* __restrict__ bias, float* __restrict__ C,
          int K, int ldc, long strideA, long strideB, long strideC)
{
    constexpr int THREADS = 32 * NWM * NWN;
    constexpr int WM = BM / NWM;
    constexpr int WN = BN / NWN;
    constexpr int MT = WM / 16;
    constexpr int NT = WN / 8;
    constexpr int ACH = (BM * 2) / THREADS;   // 8-float chunks of A per thread
    constexpr int BCH = (BN * 2) / THREADS;

    __shared__ __align__(16) uint16_t sAh[2][BM * SPH];
    __shared__ __align__(16) uint16_t sAl[2][BM * SPH];
    __shared__ __align__(16) uint16_t sBh[2][BN * SPH];
    __shared__ __align__(16) uint16_t sBl[2][BN * SPH];

    const int z = blockIdx.z;
    if (PVMODE) {
        // z = b*16 + h ; A = w in (H,B,T,T); B = vT[bh]; C = attn merged (B,T,E)
        int b = z >> 4, h = z & 15;
        A += (size_t)(h * BATCH + b) * TSEQ * TSEQ;
        B += (size_t)z * HDIM * TSEQ;
        C += (size_t)b * TSEQ * EMB + (size_t)h * HDIM;
    } else {
        A += (size_t)z * strideA;
        B += (size_t)z * strideB;
        C += (size_t)z * strideC;
    }
    const int m0 = blockIdx.y * BM;
    const int n0 = blockIdx.x * BN;

    const int tid = threadIdx.x;
    const int lane = tid & 31, wid = tid >> 5;
    const int wm = wid % NWM, wn = wid / NWM;

    float acc[MT][NT][4];
#pragma unroll
    for (int i = 0; i < MT; i++)
#pragma unroll
        for (int j = 0; j < NT; j++)
#pragma unroll
            for (int r = 0; r < 4; r++) acc[i][j][r] = 0.0f;

    float4 ra[ACH][2], rb[BCH][2];

    auto ldg_stage = [&](int k0) {
#pragma unroll
        for (int i = 0; i < ACH; i++) {
            int c = tid + i * THREADS;
            int r = c >> 1, k8 = (c & 1) * 8;
            const float4* p = (const float4*)(A + (size_t)(m0 + r) * K + k0 + k8);
            ra[i][0] = p[0]; ra[i][1] = p[1];
        }
#pragma unroll
        for (int i = 0; i < BCH; i++) {
            int c = tid + i * THREADS;
            int r = c >> 1, k8 = (c & 1) * 8;
            const float4* p = (const float4*)(B + (size_t)(n0 + r) * K + k0 + k8);
            rb[i][0] = p[0]; rb[i][1] = p[1];
        }
    };
    auto sts_stage = [&](int buf) {
#pragma unroll
        for (int i = 0; i < ACH; i++) {
            int c = tid + i * THREADS;
            int r = c >> 1, k8 = (c & 1) * 8;
            uint4 h, l;
            cvt8(ra[i][0], ra[i][1], h, l);
            *(uint4*)&sAh[buf][r * SPH + k8] = h;
            *(uint4*)&sAl[buf][r * SPH + k8] = l;
        }
#pragma unroll
        for (int i = 0; i < BCH; i++) {
            int c = tid + i * THREADS;
            int r = c >> 1, k8 = (c & 1) * 8;
            uint4 h, l;
            cvt8(rb[i][0], rb[i][1], h, l);
            *(uint4*)&sBh[buf][r * SPH + k8] = h;
            *(uint4*)&sBl[buf][r * SPH + k8] = l;
        }
    };

    const int ntiles = K / BK;
    ldg_stage(0);

    for (int it = 0; it < ntiles; it++) {
        const int buf = it & 1;
        sts_stage(buf);
        if (it + 1 < ntiles) ldg_stage((it + 1) * BK);
        __syncthreads();

        const uint16_t* cAh = sAh[buf];
        const uint16_t* cAl = sAl[buf];
        const uint16_t* cBh = sBh[buf];
        const uint16_t* cBl = sBl[buf];

        const int kc = (lane & 3) * 2;
        uint32_t ah[MT][4], al[MT][4];
#pragma unroll
        for (int mt = 0; mt < MT; mt++) {
            int r = wm * WM + mt * 16 + (lane >> 2);
            int o = r * SPH + kc;
            ah[mt][0] = *(const uint32_t*)&cAh[o];
            ah[mt][1] = *(const uint32_t*)&cAh[o + 8 * SPH];
            ah[mt][2] = *(const uint32_t*)&cAh[o + 8];
            ah[mt][3] = *(const uint32_t*)&cAh[o + 8 * SPH + 8];
            al[mt][0] = *(const uint32_t*)&cAl[o];
            al[mt][1] = *(const uint32_t*)&cAl[o + 8 * SPH];
            al[mt][2] = *(const uint32_t*)&cAl[o + 8];
            al[mt][3] = *(const uint32_t*)&cAl[o + 8 * SPH + 8];
        }
        uint32_t bh[NT][2], bl[NT][2];
#pragma unroll
        for (int nt = 0; nt < NT; nt++) {
            int n = wn * WN + nt * 8 + (lane >> 2);
            int o = n * SPH + kc;
            bh[nt][0] = *(const uint32_t*)&cBh[o];
            bh[nt][1] = *(const uint32_t*)&cBh[o + 8];
            bl[nt][0] = *(const uint32_t*)&cBl[o];
            bl[nt][1] = *(const uint32_t*)&cBl[o + 8];
        }
#pragma unroll
        for (int mt = 0; mt < MT; mt++)
#pragma unroll
            for (int nt = 0; nt < NT; nt++) {
                mma_bf16(acc[mt][nt], ah[mt], bl[nt]);
                mma_bf16(acc[mt][nt], al[mt], bh[nt]);
                mma_bf16(acc[mt][nt], ah[mt], bh[nt]);
            }
        __syncthreads();
    }

    // epilogue (C fragment layout identical to m16n8 tf32 path)
#pragma unroll
    for (int mt = 0; mt < MT; mt++) {
        int r0 = m0 + wm * WM + mt * 16 + (lane >> 2);
#pragma unroll
        for (int nt = 0; nt < NT; nt++) {
            int c0 = n0 + wn * WN + nt * 8 + (lane & 3) * 2;
            float b0 = 0.0f, b1 = 0.0f;
            if (bias) { b0 = bias[c0]; b1 = bias[c0 + 1]; }
            float2 v0 = make_float2(acc[mt][nt][0] + b0, acc[mt][nt][1] + b1);
            float2 v1 = make_float2(acc[mt][nt][2] + b0, acc[mt][nt][3] + b1);
            *(float2*)&C[(size_t)r0 * ldc + c0]       = v0;
            *(float2*)&C[(size_t)(r0 + 8) * ldc + c0] = v1;
        }
    }
}

// ---------------- pruning (exact top-512) + xpos + split-heads ----------------
__global__ __launch_bounds__(256)
void prune_xpos_kernel() {
    const int n   = blockIdx.x;
    const int sel = blockIdx.y;        // 0=q, 1=k, 2=v
    const int b   = n >> 11;
    const int t   = n & (TSEQ - 1);
    const int tid = threadIdx.x;

    __shared__ float    row[EMB];
    __shared__ unsigned key[EMB];
    __shared__ int      cnt;

    const float scl = (sel == 0) ? 0.125f : 1.0f;
#pragma unroll
    for (int i = tid; i < EMB; i += 256) {
        float x = g_proj[sel][n][i] * scl;
        row[i] = x;
        unsigned u = __float_as_uint(x);
        key[i] = (u & 0x80000000u) ? ~u : (u | 0x80000000u);
    }
    __syncthreads();

    unsigned lo = 0u, hi = 0xFFFFFFFFu;
    while (lo < hi) {
        unsigned mid = lo + ((hi - lo) >> 1) + 1u;
        if (tid == 0) cnt = 0;
        __syncthreads();
        int c = 0;
        for (int i = tid; i < EMB; i += 256) c += (key[i] >= mid) ? 1 : 0;
#pragma unroll
        for (int off = 16; off; off >>= 1) c += __shfl_xor_sync(0xffffffffu, c, off);
        if ((tid & 31) == 0) atomicAdd(&cnt, c);
        __syncthreads();
        if (cnt >= KTOP) lo = mid; else hi = mid - 1u;
        __syncthreads();
    }
    const unsigned thr = lo;

    for (int i = tid; i < EMB; i += 256) {
        float xp = (key[i] >= thr) ? row[i] : 0.0f;
        int h = i >> 6, d = i & 63, j = (i & 63) >> 1;
        if (sel == 2) {
            g_vT[b * HEADS + h][d][t] = xp;       // transposed V for tensor-core PV
        } else {
            int ip = i ^ 1;
            float xo = (key[ip] >= thr) ? row[ip] : 0.0f;
            float ss, cs;
            if (sel == 0) { ss = g_sinq[t][j]; cs = g_cosq[t][j]; }
            else          { ss = g_sink[t][j]; cs = g_cosk[t][j]; }
            float rot = (d & 1) ? xo : -xo;
            g_qkvh[sel][b * HEADS + h][t][d] = fmaf(xp, cs, rot * ss);
        }
    }
}

// ---------------- row softmax + fp16 round -> attn_weights output ------------------
__global__ __launch_bounds__(256)
void softmax_kernel(const float* __restrict__ S, float* __restrict__ Wout)
{
    const long rowid = blockIdx.x;
    const int bh = (int)(rowid >> 11);
    const int t  = (int)(rowid & (TSEQ - 1));
    const int b  = bh >> 4, h = bh & 15;
    const float* src = S + (size_t)rowid * TSEQ;
    float* dst = Wout + (((size_t)(h * BATCH + b) * TSEQ + t) * TSEQ);

    const int tid = threadIdx.x;
    const int lane = tid & 31, wid = tid >> 5;
    __shared__ float red[8];

    float v[8];
    float m = -3.402823466e38f;
#pragma unroll
    for (int i = 0; i < 8; i++) { v[i] = src[tid + i * 256]; m = fmaxf(m, v[i]); }
#pragma unroll
    for (int off = 16; off; off >>= 1) m = fmaxf(m, __shfl_xor_sync(0xffffffffu, m, off));
    if (lane == 0) red[wid] = m;
    __syncthreads();
    float mx = red[0];
#pragma unroll
    for (int i = 1; i < 8; i++) mx = fmaxf(mx, red[i]);
    __syncthreads();

    float sum = 0.0f;
#pragma unroll
    for (int i = 0; i < 8; i++) { v[i] = expf(v[i] - mx); sum += v[i]; }
#pragma unroll
    for (int off = 16; off; off >>= 1) sum += __shfl_xor_sync(0xffffffffu, sum, off);
    if (lane == 0) red[wid] = sum;
    __syncthreads();
    float tot = 0.0f;
#pragma unroll
    for (int i = 0; i < 8; i++) tot += red[i];
    const float inv = 1.0f / tot;
#pragma unroll
    for (int i = 0; i < 8; i++) {
        float p = v[i] * inv;
        dst[tid + i * 256] = __half2float(__float2half_rn(p));
    }
}

// ---------------- launch ----------------------------------------------------------------
extern "C" void kernel_launch(void* const* d_in, const int* in_sizes, int n_in,
                              void* d_out, int out_size)
{
    (void)in_sizes; (void)n_in; (void)out_size;
    const float* query = (const float*)d_in[0];
    const float* keyx  = (const float*)d_in[1];
    const float* value = (const float*)d_in[2];
    const float* Wq = (const float*)d_in[3];
    const float* bq = (const float*)d_in[4];
    const float* Wk = (const float*)d_in[5];
    const float* bk = (const float*)d_in[6];
    const float* Wv = (const float*)d_in[7];
    const float* bv = (const float*)d_in[8];
    const float* Wo = (const float*)d_in[9];
    const float* bo = (const float*)d_in[10];

    float* out  = (float*)d_out;                 // (B,T,E) fp32
    float* wout = out + (size_t)NROWS * EMB;     // (H,B,T,T) fp32(fp16-rounded)

    float *proj, *qkvh, *vT, *scores, *attn;
    cudaGetSymbolAddress((void**)&proj,   g_proj);
    cudaGetSymbolAddress((void**)&qkvh,   g_qkvh);
    cudaGetSymbolAddress((void**)&vT,     g_vT);
    cudaGetSymbolAddress((void**)&scores, g_scores);
    cudaGetSymbolAddress((void**)&attn,   g_attn);

    // 1. xpos tables
    xpos_table_kernel<<<TSEQ, 32>>>();

    // 2. QKV projections: X(4096x1024) @ W^T + b   (3xBF16 tensor cores)
    dim3 gproj(EMB / 128, NROWS / 128, 1);
    bf16_gemm<128,128,2,4,false><<<gproj, 256>>>(query, Wq, bq, proj,
        EMB, EMB, 0, 0, 0);
    bf16_gemm<128,128,2,4,false><<<gproj, 256>>>(keyx,  Wk, bk, proj + (size_t)NROWS * EMB,
        EMB, EMB, 0, 0, 0);
    bf16_gemm<128,128,2,4,false><<<gproj, 256>>>(value, Wv, bv, proj + (size_t)2 * NROWS * EMB,
        EMB, EMB, 0, 0, 0);

    // 3. prune (exact top-512) + xpos + split heads (+ V transpose)
    prune_xpos_kernel<<<dim3(NROWS, 3), 256>>>();

    // 4. scores: per-head Q(2048x64) @ K^T -> g_scores  (3xBF16)
    const long TD = (long)TSEQ * HDIM;
    const long TT = (long)TSEQ * TSEQ;
    bf16_gemm<128,128,2,4,false><<<dim3(TSEQ/128, TSEQ/128, BHX), 256>>>(
        qkvh, qkvh + (size_t)BHX * TD, nullptr, scores,
        HDIM, TSEQ, TD, TD, TT);

    // 5. softmax + fp16 round -> attn_weights output (H,B,T,T)
    softmax_kernel<<<BHX * TSEQ, 256>>>(scores, wout);

    // 6. PV: w (fp16-exact in bf16 hi+lo) @ vT^T -> merged (B,T,E)
    bf16_gemm<128,64,2,2,true><<<dim3(1, TSEQ/128, BHX), 128>>>(
        wout, vT, nullptr, attn,
        TSEQ, EMB, 0, 0, 0);

    // 7. output projection -> out  (3xBF16)
    bf16_gemm<128,128,2,4,false><<<gproj, 256>>>(attn, Wo, bo, out,
        EMB, EMB, 0, 0, 0);
}